// round 3
// baseline (speedup 1.0000x reference)
#include <cuda_runtime.h>
#include <cuda_bf16.h>
#include <cstdint>

// ======================= problem sizes (fixed by dataset) ====================
#define TOKENS 4096
#define IC     4096
#define OC     4096
#define NOUTP  256   // outlier columns padded 204 -> 256

// ======================= device scratch (no runtime alloc) ==================
__device__ int8_t g_x8h[(size_t)TOKENS * IC];   // 16 MB  x hi plane (15-bit fixed pt)
__device__ int8_t g_x8l[(size_t)TOKENS * IC];   // 16 MB  x lo plane
__device__ int8_t g_s8 [(size_t)OC * IC];       // 16 MB  sign matrix (outlier cols 0)
__device__ __nv_bfloat16 g_xoh[(size_t)TOKENS * NOUTP];
__device__ __nv_bfloat16 g_xol[(size_t)TOKENS * NOUTP];
__device__ __nv_bfloat16 g_owh[(size_t)OC * NOUTP];
__device__ __nv_bfloat16 g_owl[(size_t)OC * NOUTP];
__device__ float g_mean[OC];
__device__ float g_scale[OC];
__device__ float g_qt[TOKENS];
__device__ int   g_map[IC];

// ======================= helpers =============================================
__device__ __forceinline__ uint32_t smem_u32(const void* p) {
    uint32_t a;
    asm("{ .reg .u64 t; cvta.to.shared.u64 t, %1; cvt.u32.u64 %0, t; }"
        : "=r"(a) : "l"(p));
    return a;
}

#define CP_ASYNC16(saddr, gaddr) \
    asm volatile("cp.async.cg.shared.global [%0], [%1], 16;" \
                 :: "r"(saddr), "l"(gaddr))
#define CP_COMMIT() asm volatile("cp.async.commit_group;" ::: "memory")
#define CP_WAIT2()  asm volatile("cp.async.wait_group 2;" ::: "memory")

#define LDMATRIX_X4(r0, r1, r2, r3, addr) \
    asm volatile("ldmatrix.sync.aligned.m8n8.x4.shared.b16 {%0,%1,%2,%3}, [%4];" \
                 : "=r"(r0), "=r"(r1), "=r"(r2), "=r"(r3) : "r"(addr))

#define MMA16816(d, a, b0, b1) \
    asm volatile("mma.sync.aligned.m16n8k16.row.col.f32.bf16.bf16.f32 " \
                 "{%0,%1,%2,%3}, {%4,%5,%6,%7}, {%8,%9}, {%0,%1,%2,%3};" \
                 : "+f"((d)[0]), "+f"((d)[1]), "+f"((d)[2]), "+f"((d)[3]) \
                 : "r"((a)[0]), "r"((a)[1]), "r"((a)[2]), "r"((a)[3]), \
                   "r"(b0), "r"(b1))

#define MMAI16832(d, a, b0, b1) \
    asm volatile("mma.sync.aligned.m16n8k32.row.col.s32.s8.s8.s32 " \
                 "{%0,%1,%2,%3}, {%4,%5,%6,%7}, {%8,%9}, {%0,%1,%2,%3};" \
                 : "+r"((d)[0]), "+r"((d)[1]), "+r"((d)[2]), "+r"((d)[3]) \
                 : "r"((a)[0]), "r"((a)[1]), "r"((a)[2]), "r"((a)[3]), \
                   "r"(b0), "r"(b1))

// ======================= prep kernels (vectorized) ===========================
__global__ void row_stats_kernel(const float* __restrict__ w) {
    __shared__ float red[256];
    int o = blockIdx.x, tid = threadIdx.x;
    const float4* row = (const float4*)(w + (size_t)o * IC);
    float4 v[4];
    float s = 0.f;
#pragma unroll
    for (int i = 0; i < 4; ++i) {
        v[i] = row[tid + 256 * i];
        s += v[i].x + v[i].y + v[i].z + v[i].w;
    }
    red[tid] = s;
    __syncthreads();
    for (int st = 128; st > 0; st >>= 1) {
        if (tid < st) red[tid] += red[tid + st];
        __syncthreads();
    }
    float mean = red[0] * (1.f / IC);
    __syncthreads();
    float a = 0.f;
#pragma unroll
    for (int i = 0; i < 4; ++i)
        a += fabsf(v[i].x - mean) + fabsf(v[i].y - mean) +
             fabsf(v[i].z - mean) + fabsf(v[i].w - mean);
    red[tid] = a;
    __syncthreads();
    for (int st = 128; st > 0; st >>= 1) {
        if (tid < st) red[tid] += red[tid + st];
        __syncthreads();
    }
    if (tid == 0) {
        g_mean[o] = mean;
        g_scale[o] = red[0] * (1.f / IC);
    }
}

__global__ void map_init_kernel() {
    int i = blockIdx.x * 256 + threadIdx.x;
    if (i < IC) g_map[i] = -1;
}
__global__ void map_scatter_kernel(const int* __restrict__ idx, int nout) {
    int j = blockIdx.x * 256 + threadIdx.x;
    if (j < nout) g_map[idx[j]] = j;
}

// per-token 15-bit fixed-point split: x ~= q_t * (256*hi8 + lo8)
__global__ void xquant_kernel(const float* __restrict__ x) {
    __shared__ float red[256];
    int t = blockIdx.x, tid = threadIdx.x;
    const float4* row = (const float4*)(x + (size_t)t * IC);
    float4 v[4];
    float m = 0.f;
#pragma unroll
    for (int i = 0; i < 4; ++i) {
        v[i] = row[tid + 256 * i];
        m = fmaxf(m, fmaxf(fmaxf(fabsf(v[i].x), fabsf(v[i].y)),
                           fmaxf(fabsf(v[i].z), fabsf(v[i].w))));
    }
    red[tid] = m;
    __syncthreads();
    for (int st = 128; st > 0; st >>= 1) {
        if (tid < st) red[tid] = fmaxf(red[tid], red[tid + st]);
        __syncthreads();
    }
    float absmax = red[0];
    float inv = (absmax > 0.f) ? (32256.f / absmax) : 0.f;
    if (tid == 0) g_qt[t] = (absmax > 0.f) ? (absmax / 32256.f) : 0.f;
    uint32_t* ph = (uint32_t*)g_x8h + ((size_t)t * IC >> 2);
    uint32_t* pl = (uint32_t*)g_x8l + ((size_t)t * IC >> 2);
#pragma unroll
    for (int i = 0; i < 4; ++i) {
        float e[4] = {v[i].x, v[i].y, v[i].z, v[i].w};
        uint32_t hp = 0, lp = 0;
#pragma unroll
        for (int k = 0; k < 4; ++k) {
            int vv = __float2int_rn(e[k] * inv);
            int lo = (int)(int8_t)(vv & 0xFF);
            int hi = (vv - lo) >> 8;
            hp |= (uint32_t)(hi & 0xFF) << (8 * k);
            lp |= (uint32_t)(lo & 0xFF) << (8 * k);
        }
        ph[tid + 256 * i] = hp;
        pl[tid + 256 * i] = lp;
    }
}

// sign matrix as int8 {-1,0,1}, outlier cols zeroed; 8 elems / thread
__global__ void build_ws_kernel(const float* __restrict__ w) {
    size_t base = ((size_t)blockIdx.x * 256 + threadIdx.x) * 8;
    int o = (int)(base >> 12);
    int i0 = (int)(base & (IC - 1));
    float mean = g_mean[o];
    float4 w0 = *(const float4*)(w + base);
    float4 w1 = *(const float4*)(w + base + 4);
    float wv[8] = {w0.x, w0.y, w0.z, w0.w, w1.x, w1.y, w1.z, w1.w};
    uint32_t p0 = 0, p1 = 0;
#pragma unroll
    for (int e = 0; e < 8; ++e) {
        int sv = 0;
        if (g_map[i0 + e] < 0) {
            float wc = wv[e] - mean;
            sv = (wc > 0.f) - (wc < 0.f);
        }
        if (e < 4) p0 |= (uint32_t)(sv & 0xFF) << (8 * e);
        else       p1 |= (uint32_t)(sv & 0xFF) << (8 * (e - 4));
    }
    *(uint2*)(g_s8 + base) = make_uint2(p0, p1);
}

__device__ __forceinline__ uint32_t pack_bf16(__nv_bfloat16 a, __nv_bfloat16 b) {
    return (uint32_t)__bfloat16_as_ushort(a) | ((uint32_t)__bfloat16_as_ushort(b) << 16);
}

__global__ void build_xout_kernel(const float* __restrict__ x,
                                  const int* __restrict__ idx, int nout) {
    int g = blockIdx.x * 256 + threadIdx.x;
    if (g >= TOKENS * NOUTP / 4) return;
    int tok = g >> 6;
    int j0 = (g & 63) * 4;
    __nv_bfloat16 hi[4], lo[4];
#pragma unroll
    for (int e = 0; e < 4; ++e) {
        int j = j0 + e;
        float xv = (j < nout) ? x[(size_t)tok * IC + idx[j]] : 0.f;
        hi[e] = __float2bfloat16(xv);
        lo[e] = __float2bfloat16(xv - __bfloat162float(hi[e]));
    }
    size_t off = (size_t)tok * NOUTP + j0;
    *(uint2*)(g_xoh + off) = make_uint2(pack_bf16(hi[0], hi[1]), pack_bf16(hi[2], hi[3]));
    *(uint2*)(g_xol + off) = make_uint2(pack_bf16(lo[0], lo[1]), pack_bf16(lo[2], lo[3]));
}

__global__ void build_ow_kernel(const float* __restrict__ ow, int nout) {
    int g = blockIdx.x * 256 + threadIdx.x;
    if (g >= OC * NOUTP / 4) return;
    int o = g >> 6;
    int j0 = (g & 63) * 4;
    __nv_bfloat16 hi[4], lo[4];
#pragma unroll
    for (int e = 0; e < 4; ++e) {
        int j = j0 + e;
        float v = (j < nout) ? ow[(size_t)o * nout + j] : 0.f;
        hi[e] = __float2bfloat16(v);
        lo[e] = __float2bfloat16(v - __bfloat162float(hi[e]));
    }
    size_t off = (size_t)o * NOUTP + j0;
    *(uint2*)(g_owh + off) = make_uint2(pack_bf16(hi[0], hi[1]), pack_bf16(hi[2], hi[3]));
    *(uint2*)(g_owl + off) = make_uint2(pack_bf16(lo[0], lo[1]), pack_bf16(lo[2], lo[3]));
}

// ======================= int8 binary GEMM ====================================
// CTA 128x128, BK=128 int8 bytes. 8 warps (2m x 4n), warp tile 64x32.
// kt 0..31: hi plane; acc *= 256; kt 32..63: lo plane (same B).
// Epilogue: out = float(acc) * q_t[row] * s_o[col] + bias[col].
static constexpr int ISTAGE = 32768;       // A 16KB + B 16KB
static constexpr int IOFF_B = 16384;
static constexpr int ISMEM  = 3 * ISTAGE;  // 96 KB

__global__ void __launch_bounds__(256, 2)
gemm_int_kernel(float* __restrict__ out, const float* __restrict__ bias) {
    extern __shared__ __align__(1024) char smem[];
    const uint32_t sbase = smem_u32(smem);
    const int tid = threadIdx.x;
    const int bn = blockIdx.x, bm = blockIdx.y;
    const int wid = tid >> 5, lane = tid & 31;
    const int wm = wid >> 2, wn = wid & 3;

    int acc[4][4][4];
#pragma unroll
    for (int i = 0; i < 4; ++i)
#pragma unroll
        for (int j = 0; j < 4; ++j)
#pragma unroll
            for (int k = 0; k < 4; ++k) acc[i][j][k] = 0;

    auto issue = [&](int kt, int s) {
        const int8_t* ap = (kt < 32 ? g_x8h : g_x8l) +
                           (size_t)bm * 128 * IC + (kt & 31) * 128;
        const int8_t* bp = g_s8 + (size_t)bn * 128 * IC + (kt & 31) * 128;
        uint32_t st = sbase + s * ISTAGE;
#pragma unroll
        for (int i = 0; i < 4; ++i) {
            int c = tid + i * 256;
            int row = c >> 3, ch = c & 7;
            uint32_t so = (uint32_t)row * 128 + (uint32_t)((ch ^ (row & 7)) << 4);
            CP_ASYNC16(st + so, ap + (size_t)row * IC + ch * 16);
            CP_ASYNC16(st + IOFF_B + so, bp + (size_t)row * IC + ch * 16);
        }
    };

    auto compute = [&](int s) {
        uint32_t stA = sbase + s * ISTAGE;
        uint32_t stB = stA + IOFF_B;
#pragma unroll
        for (int ks = 0; ks < 4; ++ks) {
            int ch = 2 * ks + (lane >> 4);
            uint32_t bfr[2][4];
#pragma unroll
            for (int g = 0; g < 2; ++g) {
                int row = wn * 32 + g * 16 + (lane & 15);
                uint32_t ad = stB + (uint32_t)row * 128 + (uint32_t)((ch ^ (row & 7)) << 4);
                LDMATRIX_X4(bfr[g][0], bfr[g][1], bfr[g][2], bfr[g][3], ad);
            }
            uint32_t afr[4][4];
#pragma unroll
            for (int mi = 0; mi < 4; ++mi) {
                int row = wm * 64 + mi * 16 + (lane & 15);
                uint32_t ad = stA + (uint32_t)row * 128 + (uint32_t)((ch ^ (row & 7)) << 4);
                LDMATRIX_X4(afr[mi][0], afr[mi][1], afr[mi][2], afr[mi][3], ad);
            }
#pragma unroll
            for (int mi = 0; mi < 4; ++mi)
#pragma unroll
                for (int g = 0; g < 2; ++g) {
                    MMAI16832(acc[mi][2 * g],     afr[mi], bfr[g][0], bfr[g][2]);
                    MMAI16832(acc[mi][2 * g + 1], afr[mi], bfr[g][1], bfr[g][3]);
                }
        }
    };

    issue(0, 0); CP_COMMIT();
    issue(1, 1); CP_COMMIT();
    for (int kt = 0; kt < 64; ++kt) {
        if (kt + 2 < 64) issue(kt + 2, (kt + 2) % 3);
        CP_COMMIT();
        CP_WAIT2();
        __syncthreads();
        compute(kt % 3);
        if (kt == 31) {
#pragma unroll
            for (int i = 0; i < 4; ++i)
#pragma unroll
                for (int j = 0; j < 4; ++j)
#pragma unroll
                    for (int k = 0; k < 4; ++k) acc[i][j][k] *= 256;
        }
        __syncthreads();
    }

    // epilogue: out = acc * q_t * s_o + bias
#pragma unroll
    for (int mi = 0; mi < 4; ++mi) {
        int r0 = bm * 128 + wm * 64 + mi * 16 + (lane >> 2);
        float qa = g_qt[r0], qb = g_qt[r0 + 8];
#pragma unroll
        for (int nf = 0; nf < 4; ++nf) {
            int c = bn * 128 + wn * 32 + (nf >> 1) * 16 + (nf & 1) * 8 + 2 * (lane & 3);
            float s0 = g_scale[c], s1 = g_scale[c + 1];
            float b0 = __ldg(bias + c), b1 = __ldg(bias + c + 1);
            float2 v0 = make_float2((float)acc[mi][nf][0] * qa * s0 + b0,
                                    (float)acc[mi][nf][1] * qa * s1 + b1);
            *(float2*)(out + (size_t)r0 * OC + c) = v0;
            float2 v1 = make_float2((float)acc[mi][nf][2] * qb * s0 + b0,
                                    (float)acc[mi][nf][3] * qb * s1 + b1);
            *(float2*)(out + (size_t)(r0 + 8) * OC + c) = v1;
        }
    }
}

// ======================= outlier bf16 GEMM (RMW) =============================
// CTA 128x128, K=256, 3 terms: xh*owh, xl*owh, xh*owl. out += acc.
static constexpr int OSTAGE = 32768;       // A 16KB + B 16KB (bf16 128x64)
static constexpr int OOFF_B = 16384;
static constexpr int OSMEM  = 3 * OSTAGE;

__global__ void __launch_bounds__(256, 2)
gemm_out_kernel(float* __restrict__ out) {
    extern __shared__ __align__(1024) char smem[];
    const uint32_t sbase = smem_u32(smem);
    const int tid = threadIdx.x;
    const int bn = blockIdx.x, bm = blockIdx.y;
    const int wid = tid >> 5, lane = tid & 31;
    const int wm = wid >> 2, wn = wid & 3;

    float acc[4][4][4];
#pragma unroll
    for (int i = 0; i < 4; ++i)
#pragma unroll
        for (int j = 0; j < 4; ++j)
#pragma unroll
            for (int k = 0; k < 4; ++k) acc[i][j][k] = 0.f;

    auto issue = [&](int kt, int s) {
        int term = kt >> 2, koff = (kt & 3) * 64;
        const __nv_bfloat16* ap = (term == 1 ? g_xol : g_xoh) +
                                  (size_t)bm * 128 * NOUTP + koff;
        const __nv_bfloat16* bp = (term == 2 ? g_owl : g_owh) +
                                  (size_t)bn * 128 * NOUTP + koff;
        uint32_t st = sbase + s * OSTAGE;
#pragma unroll
        for (int i = 0; i < 4; ++i) {
            int c = tid + i * 256;
            int row = c >> 3, ch = c & 7;
            uint32_t so = (uint32_t)row * 128 + (uint32_t)((ch ^ (row & 7)) << 4);
            CP_ASYNC16(st + so, ap + (size_t)row * NOUTP + ch * 8);
            CP_ASYNC16(st + OOFF_B + so, bp + (size_t)row * NOUTP + ch * 8);
        }
    };

    auto compute = [&](int s) {
        uint32_t stA = sbase + s * OSTAGE;
        uint32_t stB = stA + OOFF_B;
#pragma unroll
        for (int ks = 0; ks < 4; ++ks) {
            uint32_t bfr[2][4];
#pragma unroll
            for (int g = 0; g < 2; ++g) {
                int row = wn * 32 + g * 16 + (lane & 7) + (((lane >> 4) & 1) << 3);
                int ch = ks * 2 + ((lane >> 3) & 1);
                uint32_t ad = stB + (uint32_t)row * 128 + (uint32_t)((ch ^ (row & 7)) << 4);
                LDMATRIX_X4(bfr[g][0], bfr[g][1], bfr[g][2], bfr[g][3], ad);
            }
            uint32_t afr[4][4];
#pragma unroll
            for (int mi = 0; mi < 4; ++mi) {
                int row = wm * 64 + mi * 16 + (lane & 15);
                int ch = ks * 2 + (lane >> 4);
                uint32_t ad = stA + (uint32_t)row * 128 + (uint32_t)((ch ^ (row & 7)) << 4);
                LDMATRIX_X4(afr[mi][0], afr[mi][1], afr[mi][2], afr[mi][3], ad);
            }
#pragma unroll
            for (int mi = 0; mi < 4; ++mi)
#pragma unroll
                for (int g = 0; g < 2; ++g) {
                    MMA16816(acc[mi][2 * g],     afr[mi], bfr[g][0], bfr[g][1]);
                    MMA16816(acc[mi][2 * g + 1], afr[mi], bfr[g][2], bfr[g][3]);
                }
        }
    };

    issue(0, 0); CP_COMMIT();
    issue(1, 1); CP_COMMIT();
    for (int kt = 0; kt < 12; ++kt) {
        if (kt + 2 < 12) issue(kt + 2, (kt + 2) % 3);
        CP_COMMIT();
        CP_WAIT2();
        __syncthreads();
        compute(kt % 3);
        __syncthreads();
    }

#pragma unroll
    for (int mi = 0; mi < 4; ++mi) {
        int r0 = bm * 128 + wm * 64 + mi * 16 + (lane >> 2);
#pragma unroll
        for (int nf = 0; nf < 4; ++nf) {
            int c = bn * 128 + wn * 32 + (nf >> 1) * 16 + (nf & 1) * 8 + 2 * (lane & 3);
            float2 v0 = *(float2*)(out + (size_t)r0 * OC + c);
            v0.x += acc[mi][nf][0]; v0.y += acc[mi][nf][1];
            *(float2*)(out + (size_t)r0 * OC + c) = v0;
            float2 v1 = *(float2*)(out + (size_t)(r0 + 8) * OC + c);
            v1.x += acc[mi][nf][2]; v1.y += acc[mi][nf][3];
            *(float2*)(out + (size_t)(r0 + 8) * OC + c) = v1;
        }
    }
}

// ======================= launcher ============================================
extern "C" void kernel_launch(void* const* d_in, const int* in_sizes, int n_in,
                              void* d_out, int out_size) {
    const float* x = (const float*)d_in[0];
    const float* w = (const float*)d_in[1];
    const float* bias = (const float*)d_in[2];
    const float* ow = (const float*)d_in[3];
    const int* idx = (const int*)d_in[4];
    float* out = (float*)d_out;
    int nout = in_sizes[4];

    static bool attr_set = false;
    if (!attr_set) {
        cudaFuncSetAttribute(gemm_int_kernel,
                             cudaFuncAttributeMaxDynamicSharedMemorySize, ISMEM);
        cudaFuncSetAttribute(gemm_out_kernel,
                             cudaFuncAttributeMaxDynamicSharedMemorySize, OSMEM);
        attr_set = true;
    }

    row_stats_kernel<<<OC, 256>>>(w);
    map_init_kernel<<<IC / 256, 256>>>();
    map_scatter_kernel<<<(nout + 255) / 256, 256>>>(idx, nout);
    build_ws_kernel<<<(unsigned)((size_t)OC * IC / 2048), 256>>>(w);
    xquant_kernel<<<TOKENS, 256>>>(x);
    build_xout_kernel<<<TOKENS * NOUTP / 4 / 256, 256>>>(x, idx, nout);
    build_ow_kernel<<<OC * NOUTP / 4 / 256, 256>>>(ow, nout);

    dim3 grid(OC / 128, TOKENS / 128);
    gemm_int_kernel<<<grid, 256, ISMEM>>>(out, bias);
    gemm_out_kernel<<<grid, 256, OSMEM>>>(out);
}

// round 5
// speedup vs baseline: 3.6436x; 3.6436x over previous
#include <cuda_runtime.h>
#include <cuda_bf16.h>
#include <cuda_fp16.h>
#include <cstdint>

// ======================= problem sizes (fixed by dataset) ====================
#define TOKENS 4096
#define IC     4096
#define OC     4096
#define NOUTP  256   // outlier columns padded 204 -> 256

// ======================= device scratch (no runtime alloc) ==================
__device__ uint16_t g_x16[(size_t)TOKENS * IC];   // 32 MB  x as fp16
__device__ uint16_t g_s16[(size_t)OC * IC];       // 32 MB  sign matrix fp16 (outlier cols 0)
__device__ uint16_t g_xoh[(size_t)TOKENS * NOUTP];  // bf16
__device__ uint16_t g_xol[(size_t)TOKENS * NOUTP];  // bf16
__device__ uint16_t g_owh[(size_t)OC * NOUTP];      // bf16 (ow / s_o) hi
__device__ uint16_t g_owl[(size_t)OC * NOUTP];      // bf16 (ow / s_o) lo
__device__ float g_mean[OC];
__device__ float g_scale[OC];   // 0 -> 1 (exact: then all signs are 0)
__device__ int   g_map[IC];

// ======================= helpers =============================================
__device__ __forceinline__ uint32_t smem_u32(const void* p) {
    uint32_t a;
    asm("{ .reg .u64 t; cvta.to.shared.u64 t, %1; cvt.u32.u64 %0, t; }"
        : "=r"(a) : "l"(p));
    return a;
}

#define CP_ASYNC16(saddr, gaddr) \
    asm volatile("cp.async.cg.shared.global [%0], [%1], 16;" \
                 :: "r"(saddr), "l"(gaddr))
#define CP_COMMIT() asm volatile("cp.async.commit_group;" ::: "memory")
#define CP_WAIT2()  asm volatile("cp.async.wait_group 2;" ::: "memory")

#define LDMATRIX_X4(r0, r1, r2, r3, addr) \
    asm volatile("ldmatrix.sync.aligned.m8n8.x4.shared.b16 {%0,%1,%2,%3}, [%4];" \
                 : "=r"(r0), "=r"(r1), "=r"(r2), "=r"(r3) : "r"(addr))

#define MMA_BF16(d, a, b0, b1) \
    asm volatile("mma.sync.aligned.m16n8k16.row.col.f32.bf16.bf16.f32 " \
                 "{%0,%1,%2,%3}, {%4,%5,%6,%7}, {%8,%9}, {%0,%1,%2,%3};" \
                 : "+f"((d)[0]), "+f"((d)[1]), "+f"((d)[2]), "+f"((d)[3]) \
                 : "r"((a)[0]), "r"((a)[1]), "r"((a)[2]), "r"((a)[3]), \
                   "r"(b0), "r"(b1))

#define MMA_F16(d, a, b0, b1) \
    asm volatile("mma.sync.aligned.m16n8k16.row.col.f32.f16.f16.f32 " \
                 "{%0,%1,%2,%3}, {%4,%5,%6,%7}, {%8,%9}, {%0,%1,%2,%3};" \
                 : "+f"((d)[0]), "+f"((d)[1]), "+f"((d)[2]), "+f"((d)[3]) \
                 : "r"((a)[0]), "r"((a)[1]), "r"((a)[2]), "r"((a)[3]), \
                   "r"(b0), "r"(b1))

// ======================= prep kernels (vectorized) ===========================
__global__ void row_stats_kernel(const float* __restrict__ w) {
    __shared__ float red[256];
    int o = blockIdx.x, tid = threadIdx.x;
    const float4* row = (const float4*)(w + (size_t)o * IC);
    float4 v[4];
    float s = 0.f;
#pragma unroll
    for (int i = 0; i < 4; ++i) {
        v[i] = row[tid + 256 * i];
        s += v[i].x + v[i].y + v[i].z + v[i].w;
    }
    red[tid] = s;
    __syncthreads();
    for (int st = 128; st > 0; st >>= 1) {
        if (tid < st) red[tid] += red[tid + st];
        __syncthreads();
    }
    float mean = red[0] * (1.f / IC);
    __syncthreads();
    float a = 0.f;
#pragma unroll
    for (int i = 0; i < 4; ++i)
        a += fabsf(v[i].x - mean) + fabsf(v[i].y - mean) +
             fabsf(v[i].z - mean) + fabsf(v[i].w - mean);
    red[tid] = a;
    __syncthreads();
    for (int st = 128; st > 0; st >>= 1) {
        if (tid < st) red[tid] += red[tid + st];
        __syncthreads();
    }
    if (tid == 0) {
        g_mean[o] = mean;
        float sc = red[0] * (1.f / IC);
        g_scale[o] = (sc == 0.f) ? 1.f : sc;  // sc==0 => all signs 0, so 1 is exact
    }
}

__global__ void map_init_kernel() {
    int i = blockIdx.x * 256 + threadIdx.x;
    if (i < IC) g_map[i] = -1;
}
__global__ void map_scatter_kernel(const int* __restrict__ idx, int nout) {
    int j = blockIdx.x * 256 + threadIdx.x;
    if (j < nout) g_map[idx[j]] = j;
}

// sign matrix as fp16 {-1,0,1}, outlier cols zeroed; 8 elems/thread
__global__ void build_ws_kernel(const float* __restrict__ w) {
    size_t base = ((size_t)blockIdx.x * 256 + threadIdx.x) * 8;
    int o = (int)(base >> 12);
    int i0 = (int)(base & (IC - 1));
    float mean = g_mean[o];
    float4 w0 = *(const float4*)(w + base);
    float4 w1 = *(const float4*)(w + base + 4);
    float wv[8] = {w0.x, w0.y, w0.z, w0.w, w1.x, w1.y, w1.z, w1.w};
    uint16_t hv[8];
#pragma unroll
    for (int e = 0; e < 8; ++e) {
        float sv = 0.f;
        if (g_map[i0 + e] < 0) {
            float wc = wv[e] - mean;
            sv = (wc > 0.f) ? 1.f : ((wc < 0.f) ? -1.f : 0.f);
        }
        hv[e] = __half_as_ushort(__float2half_rn(sv));
    }
    uint4 pk;
    pk.x = (uint32_t)hv[0] | ((uint32_t)hv[1] << 16);
    pk.y = (uint32_t)hv[2] | ((uint32_t)hv[3] << 16);
    pk.z = (uint32_t)hv[4] | ((uint32_t)hv[5] << 16);
    pk.w = (uint32_t)hv[6] | ((uint32_t)hv[7] << 16);
    *(uint4*)(g_s16 + base) = pk;
}

// x as fp16; 8 elems/thread
__global__ void build_x_kernel(const float* __restrict__ x) {
    size_t base = ((size_t)blockIdx.x * 256 + threadIdx.x) * 8;
    float4 v0 = *(const float4*)(x + base);
    float4 v1 = *(const float4*)(x + base + 4);
    float e[8] = {v0.x, v0.y, v0.z, v0.w, v1.x, v1.y, v1.z, v1.w};
    uint16_t hv[8];
#pragma unroll
    for (int k = 0; k < 8; ++k) hv[k] = __half_as_ushort(__float2half_rn(e[k]));
    uint4 pk;
    pk.x = (uint32_t)hv[0] | ((uint32_t)hv[1] << 16);
    pk.y = (uint32_t)hv[2] | ((uint32_t)hv[3] << 16);
    pk.z = (uint32_t)hv[4] | ((uint32_t)hv[5] << 16);
    pk.w = (uint32_t)hv[6] | ((uint32_t)hv[7] << 16);
    *(uint4*)(g_x16 + base) = pk;
}

__device__ __forceinline__ uint32_t pack_bf16(__nv_bfloat16 a, __nv_bfloat16 b) {
    return (uint32_t)__bfloat16_as_ushort(a) | ((uint32_t)__bfloat16_as_ushort(b) << 16);
}

__global__ void build_xout_kernel(const float* __restrict__ x,
                                  const int* __restrict__ idx, int nout) {
    int g = blockIdx.x * 256 + threadIdx.x;
    if (g >= TOKENS * NOUTP / 4) return;
    int tok = g >> 6;
    int j0 = (g & 63) * 4;
    __nv_bfloat16 hi[4], lo[4];
#pragma unroll
    for (int e = 0; e < 4; ++e) {
        int j = j0 + e;
        float xv = (j < nout) ? x[(size_t)tok * IC + idx[j]] : 0.f;
        hi[e] = __float2bfloat16(xv);
        lo[e] = __float2bfloat16(xv - __bfloat162float(hi[e]));
    }
    size_t off = (size_t)tok * NOUTP + j0;
    *(uint2*)(g_xoh + off) = make_uint2(pack_bf16(hi[0], hi[1]), pack_bf16(hi[2], hi[3]));
    *(uint2*)(g_xol + off) = make_uint2(pack_bf16(lo[0], lo[1]), pack_bf16(lo[2], lo[3]));
}

__global__ void build_ow_kernel(const float* __restrict__ ow, int nout) {
    int g = blockIdx.x * 256 + threadIdx.x;
    if (g >= OC * NOUTP / 4) return;
    int o = g >> 6;
    int j0 = (g & 63) * 4;
    __nv_bfloat16 hi[4], lo[4];
#pragma unroll
    for (int e = 0; e < 4; ++e) {
        int j = j0 + e;
        float v = (j < nout) ? ow[(size_t)o * nout + j] / g_scale[o] : 0.f;
        hi[e] = __float2bfloat16(v);
        lo[e] = __float2bfloat16(v - __bfloat162float(hi[e]));
    }
    size_t off = (size_t)o * NOUTP + j0;
    *(uint2*)(g_owh + off) = make_uint2(pack_bf16(hi[0], hi[1]), pack_bf16(hi[2], hi[3]));
    *(uint2*)(g_owl + off) = make_uint2(pack_bf16(lo[0], lo[1]), pack_bf16(lo[2], lo[3]));
}

// ======================= fused GEMM ==========================================
// CTA 128(tokens) x 256(out-ch), BK=64. 8 warps (2m x 4n), warp tile 64x64.
//   kt 0..63 : fp16  A=x16, B=sign16            (binary, K=4096, 1 pass)
//   kt 64..67: bf16  A=xoh, B=owh               (outlier term 1)
//   kt 68..71: bf16  A=xol, B=owh               (outlier term 2)
//   kt 72..75: bf16  A=xoh, B=owl               (outlier term 3)
// Epilogue: out = acc * s_o + bias.
static constexpr int NT = 76;
static constexpr int STAGE_BYTES = (128 + 256) * 64 * 2;  // 49152
static constexpr int OFF_B = 128 * 64 * 2;                 // 16384
static constexpr int SMEM_BYTES = 3 * STAGE_BYTES;         // 147456

__global__ void __launch_bounds__(256, 1)
gemm_kernel(float* __restrict__ out, const float* __restrict__ bias) {
    extern __shared__ __align__(1024) char smem[];
    const uint32_t sbase = smem_u32(smem);
    const int tid = threadIdx.x;
    const int bn = blockIdx.x, bm = blockIdx.y;
    const int wid = tid >> 5, lane = tid & 31;
    const int wm = wid >> 2, wn = wid & 3;

    float acc[4][8][4];
#pragma unroll
    for (int i = 0; i < 4; ++i)
#pragma unroll
        for (int j = 0; j < 8; ++j)
#pragma unroll
            for (int k = 0; k < 4; ++k) acc[i][j][k] = 0.f;

    // ---- stage loader --------------------------------------------------
    auto issue = [&](int kt, int s) {
        const uint16_t *a, *b;
        int stride;
        if (kt < 64) {
            int off = kt * 64;
            a = g_x16 + (size_t)bm * 128 * IC + off;
            b = g_s16 + (size_t)bn * 256 * IC + off;
            stride = IC;
        } else {
            int t = kt - 64;
            int term = t >> 2, koff = (t & 3) * 64;
            a = (term == 1 ? g_xol : g_xoh) + (size_t)bm * 128 * NOUTP + koff;
            b = (term == 2 ? g_owl : g_owh) + (size_t)bn * 256 * NOUTP + koff;
            stride = NOUTP;
        }
        uint32_t st = sbase + s * STAGE_BYTES;
#pragma unroll
        for (int i = 0; i < 4; ++i) {
            int c = tid + i * 256;
            int row = c >> 3, ch = c & 7;
            uint32_t so = (uint32_t)row * 128 + (uint32_t)((ch ^ (row & 7)) << 4);
            CP_ASYNC16(st + so, a + (size_t)row * stride + ch * 8);
        }
#pragma unroll
        for (int i = 0; i < 8; ++i) {
            int c = tid + i * 256;
            int row = c >> 3, ch = c & 7;
            uint32_t so = (uint32_t)row * 128 + (uint32_t)((ch ^ (row & 7)) << 4);
            CP_ASYNC16(st + OFF_B + so, b + (size_t)row * stride + ch * 8);
        }
    };

    // ---- compute on one stage (FP16: 1 = f16 mma, 0 = bf16 mma) --------
#define COMPUTE_STAGE(s, FP16)                                                  \
    {                                                                           \
        uint32_t stA = sbase + (s) * STAGE_BYTES;                               \
        uint32_t stB = stA + OFF_B;                                             \
        _Pragma("unroll")                                                       \
        for (int ks = 0; ks < 4; ++ks) {                                        \
            uint32_t bfr[4][4];                                                 \
            _Pragma("unroll")                                                   \
            for (int nj = 0; nj < 4; ++nj) {                                    \
                int row = wn * 64 + nj * 16 + (lane & 7) + (((lane >> 4) & 1) << 3); \
                int ch = ks * 2 + ((lane >> 3) & 1);                            \
                uint32_t ad = stB + (uint32_t)row * 128 +                       \
                              (uint32_t)((ch ^ (row & 7)) << 4);                \
                LDMATRIX_X4(bfr[nj][0], bfr[nj][1], bfr[nj][2], bfr[nj][3], ad);\
            }                                                                   \
            uint32_t afr[4][4];                                                 \
            _Pragma("unroll")                                                   \
            for (int mi = 0; mi < 4; ++mi) {                                    \
                int row = wm * 64 + mi * 16 + (lane & 15);                      \
                int ch = ks * 2 + (lane >> 4);                                  \
                uint32_t ad = stA + (uint32_t)row * 128 +                       \
                              (uint32_t)((ch ^ (row & 7)) << 4);                \
                LDMATRIX_X4(afr[mi][0], afr[mi][1], afr[mi][2], afr[mi][3], ad);\
            }                                                                   \
            _Pragma("unroll")                                                   \
            for (int mi = 0; mi < 4; ++mi)                                      \
                _Pragma("unroll")                                               \
                for (int nf = 0; nf < 8; ++nf) {                                \
                    if (FP16) {                                                 \
                        MMA_F16(acc[mi][nf], afr[mi],                           \
                                bfr[nf >> 1][(nf & 1) * 2],                     \
                                bfr[nf >> 1][(nf & 1) * 2 + 1]);                \
                    } else {                                                    \
                        MMA_BF16(acc[mi][nf], afr[mi],                          \
                                 bfr[nf >> 1][(nf & 1) * 2],                    \
                                 bfr[nf >> 1][(nf & 1) * 2 + 1]);               \
                    }                                                           \
                }                                                               \
        }                                                                       \
    }

    // ---- pipelined main loop -------------------------------------------
    issue(0, 0); CP_COMMIT();
    issue(1, 1); CP_COMMIT();
    for (int kt = 0; kt < NT; ++kt) {
        if (kt + 2 < NT) issue(kt + 2, (kt + 2) % 3);
        CP_COMMIT();
        CP_WAIT2();
        __syncthreads();
        if (kt < 64) {
            COMPUTE_STAGE(kt % 3, 1);
        } else {
            COMPUTE_STAGE(kt % 3, 0);
        }
        __syncthreads();
    }

    // ---- epilogue: out = acc * s_o + bias ------------------------------
#pragma unroll
    for (int nf = 0; nf < 8; ++nf) {
        int col = bn * 256 + wn * 64 + nf * 8 + 2 * (lane & 3);
        float s0 = g_scale[col], s1 = g_scale[col + 1];
        float b0 = __ldg(bias + col), b1 = __ldg(bias + col + 1);
#pragma unroll
        for (int mi = 0; mi < 4; ++mi) {
            int r0 = bm * 128 + wm * 64 + mi * 16 + (lane >> 2);
            float2 v0 = make_float2(acc[mi][nf][0] * s0 + b0,
                                    acc[mi][nf][1] * s1 + b1);
            *(float2*)(out + (size_t)r0 * OC + col) = v0;
            float2 v1 = make_float2(acc[mi][nf][2] * s0 + b0,
                                    acc[mi][nf][3] * s1 + b1);
            *(float2*)(out + (size_t)(r0 + 8) * OC + col) = v1;
        }
    }
}

// ======================= launcher ============================================
extern "C" void kernel_launch(void* const* d_in, const int* in_sizes, int n_in,
                              void* d_out, int out_size) {
    const float* x = (const float*)d_in[0];
    const float* w = (const float*)d_in[1];
    const float* bias = (const float*)d_in[2];
    const float* ow = (const float*)d_in[3];
    const int* idx = (const int*)d_in[4];
    float* out = (float*)d_out;
    int nout = in_sizes[4];

    static bool attr_set = false;
    if (!attr_set) {
        cudaFuncSetAttribute(gemm_kernel,
                             cudaFuncAttributeMaxDynamicSharedMemorySize, SMEM_BYTES);
        attr_set = true;
    }

    row_stats_kernel<<<OC, 256>>>(w);
    map_init_kernel<<<IC / 256, 256>>>();
    map_scatter_kernel<<<(nout + 255) / 256, 256>>>(idx, nout);
    build_ws_kernel<<<(unsigned)((size_t)OC * IC / 2048), 256>>>(w);
    build_x_kernel<<<(unsigned)((size_t)TOKENS * IC / 2048), 256>>>(x);
    build_xout_kernel<<<TOKENS * NOUTP / 4 / 256, 256>>>(x, idx, nout);
    build_ow_kernel<<<OC * NOUTP / 4 / 256, 256>>>(ow, nout);

    dim3 grid(OC / 256, TOKENS / 128);
    gemm_kernel<<<grid, 256, SMEM_BYTES>>>(out, bias);
}

// round 6
// speedup vs baseline: 5.1333x; 1.4088x over previous
#include <cuda_runtime.h>
#include <cuda_bf16.h>
#include <cuda_fp16.h>
#include <cstdint>

// ======================= problem sizes (fixed by dataset) ====================
#define TOKENS 4096
#define IC     4096
#define OC     4096
#define NOUTP  256   // outlier columns padded 204 -> 256

// ======================= device scratch (no runtime alloc) ==================
__device__ uint16_t g_x16[(size_t)TOKENS * IC];     // 32 MB  x as fp16
__device__ uint16_t g_s16[(size_t)OC * IC];         // 32 MB  sign matrix fp16
__device__ uint16_t g_xo16[(size_t)TOKENS * NOUTP]; // fp16 gathered outlier x
__device__ uint16_t g_ow16[(size_t)OC * NOUTP];     // fp16 (ow / s_o)
__device__ float g_scale[OC];   // 0 -> 1 (exact: then all signs are 0)
__device__ int   g_map[IC];

// ======================= helpers =============================================
__device__ __forceinline__ uint32_t smem_u32(const void* p) {
    uint32_t a;
    asm("{ .reg .u64 t; cvta.to.shared.u64 t, %1; cvt.u32.u64 %0, t; }"
        : "=r"(a) : "l"(p));
    return a;
}

#define CP_ASYNC16(saddr, gaddr) \
    asm volatile("cp.async.cg.shared.global [%0], [%1], 16;" \
                 :: "r"(saddr), "l"(gaddr))
#define CP_COMMIT() asm volatile("cp.async.commit_group;" ::: "memory")
#define CP_WAIT2()  asm volatile("cp.async.wait_group 2;" ::: "memory")

#define LDMATRIX_X4(r0, r1, r2, r3, addr) \
    asm volatile("ldmatrix.sync.aligned.m8n8.x4.shared.b16 {%0,%1,%2,%3}, [%4];" \
                 : "=r"(r0), "=r"(r1), "=r"(r2), "=r"(r3) : "r"(addr))

#define MMA_F16(d, a, b0, b1) \
    asm volatile("mma.sync.aligned.m16n8k16.row.col.f32.f16.f16.f32 " \
                 "{%0,%1,%2,%3}, {%4,%5,%6,%7}, {%8,%9}, {%0,%1,%2,%3};" \
                 : "+f"((d)[0]), "+f"((d)[1]), "+f"((d)[2]), "+f"((d)[3]) \
                 : "r"((a)[0]), "r"((a)[1]), "r"((a)[2]), "r"((a)[3]), \
                   "r"(b0), "r"(b1))

// ======================= prep kernels ========================================
__global__ void map_init_kernel() {
    int i = blockIdx.x * 256 + threadIdx.x;
    if (i < IC) g_map[i] = -1;
}
__global__ void map_scatter_kernel(const int* __restrict__ idx, int nout) {
    int j = blockIdx.x * 256 + threadIdx.x;
    if (j < nout) g_map[idx[j]] = j;
}

// Fused: per-row mean & abs-mean of w + write fp16 sign row (outlier cols 0).
// One block per output row; row held in registers (16 floats/thread).
__global__ void stats_ws_kernel(const float* __restrict__ w) {
    __shared__ float red[256];
    int o = blockIdx.x, tid = threadIdx.x;
    const float4* row = (const float4*)(w + (size_t)o * IC);
    float4 v[4];
    float s = 0.f;
#pragma unroll
    for (int i = 0; i < 4; ++i) {
        v[i] = row[tid + 256 * i];
        s += v[i].x + v[i].y + v[i].z + v[i].w;
    }
    red[tid] = s;
    __syncthreads();
    for (int st = 128; st > 0; st >>= 1) {
        if (tid < st) red[tid] += red[tid + st];
        __syncthreads();
    }
    float mean = red[0] * (1.f / IC);
    __syncthreads();
    float a = 0.f;
#pragma unroll
    for (int i = 0; i < 4; ++i)
        a += fabsf(v[i].x - mean) + fabsf(v[i].y - mean) +
             fabsf(v[i].z - mean) + fabsf(v[i].w - mean);
    red[tid] = a;
    __syncthreads();
    for (int st = 128; st > 0; st >>= 1) {
        if (tid < st) red[tid] += red[tid + st];
        __syncthreads();
    }
    if (tid == 0) {
        float sc = red[0] * (1.f / IC);
        g_scale[o] = (sc == 0.f) ? 1.f : sc;  // sc==0 => all signs 0, so 1 is exact
    }
    // write fp16 sign row: thread owns elems (tid + 256*i)*4 .. +3
#pragma unroll
    for (int i = 0; i < 4; ++i) {
        int e0 = (tid + 256 * i) * 4;
        float ev[4] = {v[i].x, v[i].y, v[i].z, v[i].w};
        uint16_t hv[4];
#pragma unroll
        for (int e = 0; e < 4; ++e) {
            float sv = 0.f;
            if (g_map[e0 + e] < 0) {
                float wc = ev[e] - mean;
                sv = (wc > 0.f) ? 1.f : ((wc < 0.f) ? -1.f : 0.f);
            }
            hv[e] = __half_as_ushort(__float2half_rn(sv));
        }
        uint2 pk;
        pk.x = (uint32_t)hv[0] | ((uint32_t)hv[1] << 16);
        pk.y = (uint32_t)hv[2] | ((uint32_t)hv[3] << 16);
        *(uint2*)(g_s16 + (size_t)o * IC + e0) = pk;
    }
}

// x as fp16; 8 elems/thread
__global__ void build_x_kernel(const float* __restrict__ x) {
    size_t base = ((size_t)blockIdx.x * 256 + threadIdx.x) * 8;
    float4 v0 = *(const float4*)(x + base);
    float4 v1 = *(const float4*)(x + base + 4);
    float e[8] = {v0.x, v0.y, v0.z, v0.w, v1.x, v1.y, v1.z, v1.w};
    uint16_t hv[8];
#pragma unroll
    for (int k = 0; k < 8; ++k) hv[k] = __half_as_ushort(__float2half_rn(e[k]));
    uint4 pk;
    pk.x = (uint32_t)hv[0] | ((uint32_t)hv[1] << 16);
    pk.y = (uint32_t)hv[2] | ((uint32_t)hv[3] << 16);
    pk.z = (uint32_t)hv[4] | ((uint32_t)hv[5] << 16);
    pk.w = (uint32_t)hv[6] | ((uint32_t)hv[7] << 16);
    *(uint4*)(g_x16 + base) = pk;
}

__global__ void build_xout_kernel(const float* __restrict__ x,
                                  const int* __restrict__ idx, int nout) {
    int g = blockIdx.x * 256 + threadIdx.x;
    if (g >= TOKENS * NOUTP / 4) return;
    int tok = g >> 6;
    int j0 = (g & 63) * 4;
    uint16_t hv[4];
#pragma unroll
    for (int e = 0; e < 4; ++e) {
        int j = j0 + e;
        float xv = (j < nout) ? x[(size_t)tok * IC + idx[j]] : 0.f;
        hv[e] = __half_as_ushort(__float2half_rn(xv));
    }
    *(uint2*)(g_xo16 + (size_t)tok * NOUTP + j0) =
        make_uint2((uint32_t)hv[0] | ((uint32_t)hv[1] << 16),
                   (uint32_t)hv[2] | ((uint32_t)hv[3] << 16));
}

__global__ void build_ow_kernel(const float* __restrict__ ow, int nout) {
    int g = blockIdx.x * 256 + threadIdx.x;
    if (g >= OC * NOUTP / 4) return;
    int o = g >> 6;
    int j0 = (g & 63) * 4;
    float inv_s = 1.f / g_scale[o];
    uint16_t hv[4];
#pragma unroll
    for (int e = 0; e < 4; ++e) {
        int j = j0 + e;
        float v = (j < nout) ? ow[(size_t)o * nout + j] * inv_s : 0.f;
        hv[e] = __half_as_ushort(__float2half_rn(v));
    }
    *(uint2*)(g_ow16 + (size_t)o * NOUTP + j0) =
        make_uint2((uint32_t)hv[0] | ((uint32_t)hv[1] << 16),
                   (uint32_t)hv[2] | ((uint32_t)hv[3] << 16));
}

// ======================= fused GEMM ==========================================
// CTA 128(tokens) x 128(out-ch), BK=64, 2 CTAs/SM. 8 warps (2m x 4n),
// warp tile 64x32, all fp16 mma.
//   kt 0..63 : A=x16,  B=s16   (binary, K=4096)
//   kt 64..67: A=xo16, B=ow16  (outliers, K=256, single fp16 pass)
// Epilogue: out = acc * s_o + bias.
static constexpr int NT = 68;
static constexpr int STAGE_BYTES = (128 + 128) * 64 * 2;  // 32768
static constexpr int OFF_B = 128 * 64 * 2;                 // 16384
static constexpr int SMEM_BYTES = 3 * STAGE_BYTES;         // 98304

__global__ void __launch_bounds__(256, 2)
gemm_kernel(float* __restrict__ out, const float* __restrict__ bias) {
    extern __shared__ __align__(1024) char smem[];
    const uint32_t sbase = smem_u32(smem);
    const int tid = threadIdx.x;
    const int bn = blockIdx.x, bm = blockIdx.y;
    const int wid = tid >> 5, lane = tid & 31;
    const int wm = wid >> 2, wn = wid & 3;

    float acc[4][4][4];
#pragma unroll
    for (int i = 0; i < 4; ++i)
#pragma unroll
        for (int j = 0; j < 4; ++j)
#pragma unroll
            for (int k = 0; k < 4; ++k) acc[i][j][k] = 0.f;

    // ---- stage loader --------------------------------------------------
    auto issue = [&](int kt, int s) {
        const uint16_t *a, *b;
        int stride;
        if (kt < 64) {
            int off = kt * 64;
            a = g_x16 + (size_t)bm * 128 * IC + off;
            b = g_s16 + (size_t)bn * 128 * IC + off;
            stride = IC;
        } else {
            int koff = (kt - 64) * 64;
            a = g_xo16 + (size_t)bm * 128 * NOUTP + koff;
            b = g_ow16 + (size_t)bn * 128 * NOUTP + koff;
            stride = NOUTP;
        }
        uint32_t st = sbase + s * STAGE_BYTES;
#pragma unroll
        for (int i = 0; i < 4; ++i) {
            int c = tid + i * 256;
            int row = c >> 3, ch = c & 7;
            uint32_t so = (uint32_t)row * 128 + (uint32_t)((ch ^ (row & 7)) << 4);
            CP_ASYNC16(st + so, a + (size_t)row * stride + ch * 8);
            CP_ASYNC16(st + OFF_B + so, b + (size_t)row * stride + ch * 8);
        }
    };

    // ---- compute on one stage ------------------------------------------
    auto compute = [&](int s) {
        uint32_t stA = sbase + s * STAGE_BYTES;
        uint32_t stB = stA + OFF_B;
#pragma unroll
        for (int ks = 0; ks < 4; ++ks) {
            uint32_t bfr[2][4];
#pragma unroll
            for (int nj = 0; nj < 2; ++nj) {
                int row = wn * 32 + nj * 16 + (lane & 7) + (((lane >> 4) & 1) << 3);
                int ch = ks * 2 + ((lane >> 3) & 1);
                uint32_t ad = stB + (uint32_t)row * 128 +
                              (uint32_t)((ch ^ (row & 7)) << 4);
                LDMATRIX_X4(bfr[nj][0], bfr[nj][1], bfr[nj][2], bfr[nj][3], ad);
            }
            uint32_t afr[4][4];
#pragma unroll
            for (int mi = 0; mi < 4; ++mi) {
                int row = wm * 64 + mi * 16 + (lane & 15);
                int ch = ks * 2 + (lane >> 4);
                uint32_t ad = stA + (uint32_t)row * 128 +
                              (uint32_t)((ch ^ (row & 7)) << 4);
                LDMATRIX_X4(afr[mi][0], afr[mi][1], afr[mi][2], afr[mi][3], ad);
            }
#pragma unroll
            for (int mi = 0; mi < 4; ++mi)
#pragma unroll
                for (int nf = 0; nf < 4; ++nf)
                    MMA_F16(acc[mi][nf], afr[mi],
                            bfr[nf >> 1][(nf & 1) * 2],
                            bfr[nf >> 1][(nf & 1) * 2 + 1]);
        }
    };

    // ---- pipelined main loop -------------------------------------------
    issue(0, 0); CP_COMMIT();
    issue(1, 1); CP_COMMIT();
    for (int kt = 0; kt < NT; ++kt) {
        if (kt + 2 < NT) issue(kt + 2, (kt + 2) % 3);
        CP_COMMIT();
        CP_WAIT2();
        __syncthreads();
        compute(kt % 3);
        __syncthreads();
    }

    // ---- epilogue: out = acc * s_o + bias ------------------------------
#pragma unroll
    for (int nf = 0; nf < 4; ++nf) {
        int col = bn * 128 + wn * 32 + (nf >> 1) * 16 + (nf & 1) * 8 + 2 * (lane & 3);
        float s0 = g_scale[col], s1 = g_scale[col + 1];
        float b0 = __ldg(bias + col), b1 = __ldg(bias + col + 1);
#pragma unroll
        for (int mi = 0; mi < 4; ++mi) {
            int r0 = bm * 128 + wm * 64 + mi * 16 + (lane >> 2);
            float2 v0 = make_float2(acc[mi][nf][0] * s0 + b0,
                                    acc[mi][nf][1] * s1 + b1);
            *(float2*)(out + (size_t)r0 * OC + col) = v0;
            float2 v1 = make_float2(acc[mi][nf][2] * s0 + b0,
                                    acc[mi][nf][3] * s1 + b1);
            *(float2*)(out + (size_t)(r0 + 8) * OC + col) = v1;
        }
    }
}

// ======================= launcher ============================================
extern "C" void kernel_launch(void* const* d_in, const int* in_sizes, int n_in,
                              void* d_out, int out_size) {
    const float* x = (const float*)d_in[0];
    const float* w = (const float*)d_in[1];
    const float* bias = (const float*)d_in[2];
    const float* ow = (const float*)d_in[3];
    const int* idx = (const int*)d_in[4];
    float* out = (float*)d_out;
    int nout = in_sizes[4];

    static bool attr_set = false;
    if (!attr_set) {
        cudaFuncSetAttribute(gemm_kernel,
                             cudaFuncAttributeMaxDynamicSharedMemorySize, SMEM_BYTES);
        attr_set = true;
    }

    map_init_kernel<<<IC / 256, 256>>>();
    map_scatter_kernel<<<(nout + 255) / 256, 256>>>(idx, nout);
    stats_ws_kernel<<<OC, 256>>>(w);
    build_x_kernel<<<(unsigned)((size_t)TOKENS * IC / 2048), 256>>>(x);
    build_xout_kernel<<<TOKENS * NOUTP / 4 / 256, 256>>>(x, idx, nout);
    build_ow_kernel<<<OC * NOUTP / 4 / 256, 256>>>(ow, nout);

    dim3 grid(OC / 128, TOKENS / 128);
    gemm_kernel<<<grid, 256, SMEM_BYTES>>>(out, bias);
}